// round 3
// baseline (speedup 1.0000x reference)
#include <cuda_runtime.h>
#include <math.h>

#define T_  512
#define BB  64
#define DD  1024
#define HH  1024
#define N4  4096   // 4*HH
#define GRID 148   // <= SM count (148 B300 / 152 GB300): co-residency guaranteed
#define P2B 128    // blocks doing phase-2 GEMM work (128*8 j's = 1024)

// Scratch: zx = x@Wi + b for all timesteps (512 MB).
__device__ float g_zx[(size_t)T_ * BB * N4];

// ---- software grid barrier (sense-reversal, generation counter) -----------
__device__ unsigned int          g_bar_count = 0;
__device__ volatile unsigned int g_bar_gen   = 0;

__device__ __forceinline__ void grid_barrier()
{
    __syncthreads();
    if (threadIdx.x == 0) {
        __threadfence();                       // make my writes visible
        unsigned int gen = g_bar_gen;          // read BEFORE arriving
        if (atomicAdd(&g_bar_count, 1) == GRID - 1) {
            g_bar_count = 0;                   // reset for next use
            __threadfence();                   // reset visible before release
            g_bar_gen = gen + 1;               // release
        } else {
            while (g_bar_gen == gen) __nanosleep(64);
        }
        __threadfence();                       // acquire
    }
    __syncthreads();
}

// ---- shared memory (aliased between phases) --------------------------------
// phase1: As[16][132] (8448B) + Bs[16][128] (8192B)            = 16640 B
// phase2: A2[64][68] (17408B) + B2[64][32] (8192B) + Z[64][33] =  8448 B -> 34048 B
#define SMEM_BYTES 34048

// ---------------------------------------------------------------------------
// Phase 1 tile: g_zx[bm..bm+127, bn..bn+127] = X @ Wi + bias   (K = 1024)
// 256 threads, 8x8 per thread, KT=16, register prefetch.
// ---------------------------------------------------------------------------
__device__ void phase1_tile(char* smem_raw,
                            const float* __restrict__ X,
                            const float* __restrict__ Wi,
                            const float* __restrict__ bias,
                            int bm, int bn)
{
    const int K = DD, N = N4;
    float (*As)[132] = reinterpret_cast<float (*)[132]>(smem_raw);
    float (*Bs)[128] = reinterpret_cast<float (*)[128]>(smem_raw + 16 * 132 * 4);

    const int tid = threadIdx.x;
    const int rg = tid >> 4;
    const int cg = tid & 15;

    float acc[8][8];
#pragma unroll
    for (int i = 0; i < 8; i++)
#pragma unroll
        for (int j = 0; j < 8; j++) acc[i][j] = 0.f;

    float4 pa[2], pb[2];

#pragma unroll
    for (int i = 0; i < 2; i++) {
        int idx = tid + i * 256;
        int row = idx >> 2, kq = (idx & 3) << 2;
        pa[i] = *(const float4*)(X + (size_t)(bm + row) * K + kq);
    }
#pragma unroll
    for (int i = 0; i < 2; i++) {
        int idx = tid + i * 256;
        int kk = idx >> 5, nn = (idx & 31) << 2;
        pb[i] = *(const float4*)(Wi + (size_t)kk * N + bn + nn);
    }
#pragma unroll
    for (int i = 0; i < 2; i++) {
        int idx = tid + i * 256;
        int row = idx >> 2, kq = (idx & 3) << 2;
        As[kq + 0][row] = pa[i].x; As[kq + 1][row] = pa[i].y;
        As[kq + 2][row] = pa[i].z; As[kq + 3][row] = pa[i].w;
    }
#pragma unroll
    for (int i = 0; i < 2; i++) {
        int idx = tid + i * 256;
        int kk = idx >> 5, nn = (idx & 31) << 2;
        *(float4*)&Bs[kk][nn] = pb[i];
    }
    __syncthreads();

#pragma unroll 1
    for (int kc = 1; kc <= K / 16; kc++) {
        if (kc < K / 16) {
            int k0 = kc * 16;
#pragma unroll
            for (int i = 0; i < 2; i++) {
                int idx = tid + i * 256;
                int row = idx >> 2, kq = (idx & 3) << 2;
                pa[i] = *(const float4*)(X + (size_t)(bm + row) * K + k0 + kq);
            }
#pragma unroll
            for (int i = 0; i < 2; i++) {
                int idx = tid + i * 256;
                int kk = idx >> 5, nn = (idx & 31) << 2;
                pb[i] = *(const float4*)(Wi + (size_t)(k0 + kk) * N + bn + nn);
            }
        }
#pragma unroll
        for (int kk = 0; kk < 16; kk++) {
            float a[8], b[8];
            *(float4*)&a[0] = *(float4*)&As[kk][rg * 8];
            *(float4*)&a[4] = *(float4*)&As[kk][rg * 8 + 4];
            *(float4*)&b[0] = *(float4*)&Bs[kk][cg * 8];
            *(float4*)&b[4] = *(float4*)&Bs[kk][cg * 8 + 4];
#pragma unroll
            for (int i = 0; i < 8; i++)
#pragma unroll
                for (int j = 0; j < 8; j++)
                    acc[i][j] = fmaf(a[i], b[j], acc[i][j]);
        }
        __syncthreads();
        if (kc < K / 16) {
#pragma unroll
            for (int i = 0; i < 2; i++) {
                int idx = tid + i * 256;
                int row = idx >> 2, kq = (idx & 3) << 2;
                As[kq + 0][row] = pa[i].x; As[kq + 1][row] = pa[i].y;
                As[kq + 2][row] = pa[i].z; As[kq + 3][row] = pa[i].w;
            }
#pragma unroll
            for (int i = 0; i < 2; i++) {
                int idx = tid + i * 256;
                int kk = idx >> 5, nn = (idx & 31) << 2;
                *(float4*)&Bs[kk][nn] = pb[i];
            }
            __syncthreads();
        }
    }

#pragma unroll
    for (int i = 0; i < 8; i++) {
        int row = bm + rg * 8 + i;
#pragma unroll
        for (int j = 0; j < 8; j += 4) {
            int col = bn + cg * 8 + j;
            float4 v;
            v.x = acc[i][j + 0] + bias[col + 0];
            v.y = acc[i][j + 1] + bias[col + 1];
            v.z = acc[i][j + 2] + bias[col + 2];
            v.w = acc[i][j + 3] + bias[col + 3];
            *(float4*)(g_zx + (size_t)row * N4 + col) = v;
        }
    }
}

// ---------------------------------------------------------------------------
// Phase 2 step for one block (bid < P2B): fused h@Wh GEMM + gates.
// Block owns j in [jb, jb+8) for ALL 64 batch rows; z tile = 64 x 32
// (cols c = g*8 + jj  <->  Wh col g*1024 + jb + jj).
// ---------------------------------------------------------------------------
__device__ void phase2_step(char* smem_raw, int t, int jb,
                            const float* __restrict__ hp,   // [64,1024] prev h
                            const float* __restrict__ cp,   // [64,1024] prev c
                            const float* __restrict__ Wh,
                            float* __restrict__ ys_t,       // [64,1024]
                            float* __restrict__ c_out,
                            float* __restrict__ hT)
{
    float (*A2)[68] = reinterpret_cast<float (*)[68]>(smem_raw);
    float (*B2)[32] = reinterpret_cast<float (*)[32]>(smem_raw + 64 * 68 * 4);
    float (*Z )[33] = reinterpret_cast<float (*)[33]>(smem_raw + (64 * 68 + 64 * 32) * 4);

    const int tid = threadIdx.x;
    const int rg = tid >> 5;        // 0..7 -> rows rg*8..+7
    const int c  = tid & 31;        // z col 0..31  (g = c>>3, jj = c&7)

    float acc[8];
#pragma unroll
    for (int i = 0; i < 8; i++) acc[i] = 0.f;

#pragma unroll 1
    for (int kc = 0; kc < 16; kc++) {           // K chunks of 64
        const int k0 = kc * 64;
        // load A2[kk][row] = hp[row*H + k0+kk]  (4096 elems, 16/thread)
#pragma unroll
        for (int i = 0; i < 16; i++) {
            int idx = tid + i * 256;
            int kk = idx & 63, row = idx >> 6;
            A2[kk][row] = hp[(size_t)row * HH + k0 + kk];
        }
        // load B2[kk][g*8+jj] = Wh[(k0+kk)*4096 + g*1024 + jb + jj] (2048 elems)
#pragma unroll
        for (int i = 0; i < 8; i++) {
            int idx = tid + i * 256;
            int jj = idx & 7, g = (idx >> 3) & 3, kk = idx >> 5;
            B2[kk][(g << 3) | jj] =
                Wh[(size_t)(k0 + kk) * N4 + g * HH + jb + jj];
        }
        __syncthreads();
#pragma unroll
        for (int kk = 0; kk < 64; kk++) {
            float b = B2[kk][c];
            float4 a0 = *(float4*)&A2[kk][rg * 8];
            float4 a1 = *(float4*)&A2[kk][rg * 8 + 4];
            acc[0] = fmaf(a0.x, b, acc[0]);
            acc[1] = fmaf(a0.y, b, acc[1]);
            acc[2] = fmaf(a0.z, b, acc[2]);
            acc[3] = fmaf(a0.w, b, acc[3]);
            acc[4] = fmaf(a1.x, b, acc[4]);
            acc[5] = fmaf(a1.y, b, acc[5]);
            acc[6] = fmaf(a1.z, b, acc[6]);
            acc[7] = fmaf(a1.w, b, acc[7]);
        }
        __syncthreads();
    }

    // stage z tile to smem so each thread can gather all 4 gates of a (b,j)
#pragma unroll
    for (int i = 0; i < 8; i++) Z[rg * 8 + i][c] = acc[i];
    __syncthreads();

    const float* zx = g_zx + (size_t)t * BB * N4;
#pragma unroll
    for (int p = 0; p < 2; p++) {
        int pe = tid * 2 + p;            // 0..511
        int b_ = pe >> 3;                // 0..63
        int jj = pe & 7;
        int j  = jb + jj;
        size_t zb = (size_t)b_ * N4;

        float zi = Z[b_][0  + jj] + zx[zb + 0 * HH + j];
        float zf = Z[b_][8  + jj] + zx[zb + 1 * HH + j];
        float zg = Z[b_][16 + jj] + zx[zb + 2 * HH + j];
        float zo = Z[b_][24 + jj] + zx[zb + 3 * HH + j];

        float ig = 1.f / (1.f + expf(-zi));
        float fg = 1.f / (1.f + expf(-zf));
        float gg = tanhf(zg);
        float og = 1.f / (1.f + expf(-zo));

        float cc = fg * cp[(size_t)b_ * HH + j] + ig * gg;
        float hh = og * tanhf(cc);

        c_out[(size_t)b_ * HH + j] = cc;
        ys_t [(size_t)b_ * HH + j] = hh;
        if (hT) hT[(size_t)b_ * HH + j] = hh;
    }
}

// ---------------------------------------------------------------------------
__global__ __launch_bounds__(256, 1)
void lstm_persistent(const float* __restrict__ X,
                     const float* __restrict__ c0,
                     const float* __restrict__ h0,
                     const float* __restrict__ Wi,
                     const float* __restrict__ Wh,
                     const float* __restrict__ bias,
                     float* __restrict__ ys,
                     float* __restrict__ cT,
                     float* __restrict__ hT)
{
    __shared__ __align__(16) char smem_raw[SMEM_BYTES];
    const int bid = blockIdx.x;

    // ---- Phase 1: zx = x @ Wi + b over all T*B rows ----
    const int n_tiles = (T_ * BB / 128) * (N4 / 128);   // 256 * 32 = 8192
    for (int tt = bid; tt < n_tiles; tt += GRID) {
        int bm = (tt >> 5) * 128;          // /32 n-tiles
        int bn = (tt & 31) * 128;
        phase1_tile(smem_raw, X, Wi, bias, bm, bn);
    }
    grid_barrier();

    // ---- Phase 2: 512-step recurrence ----
    const int jb = bid * 8;
    for (int t = 0; t < T_; t++) {
        if (bid < P2B) {
            const float* hp = (t == 0) ? h0 : (ys + (size_t)(t - 1) * BB * HH);
            const float* cp = (t == 0) ? c0 : cT;
            phase2_step(smem_raw, t, jb, hp, cp, Wh,
                        ys + (size_t)t * BB * HH, cT,
                        (t == T_ - 1) ? hT : nullptr);
        }
        grid_barrier();
    }
}

// ---------------------------------------------------------------------------
extern "C" void kernel_launch(void* const* d_in, const int* in_sizes, int n_in,
                              void* d_out, int out_size)
{
    const float* x  = (const float*)d_in[0];   // [T,B,D]
    const float* c0 = (const float*)d_in[1];   // [B,H]
    const float* h0 = (const float*)d_in[2];   // [B,H]
    const float* Wi = (const float*)d_in[3];   // [D,4H]
    const float* Wh = (const float*)d_in[4];   // [H,4H]
    const float* b  = (const float*)d_in[5];   // [4H]

    float* out = (float*)d_out;
    float* ys = out;                                  // [T,B,H]
    float* cT = out + (size_t)T_ * BB * HH;           // [B,H]
    float* hT = cT + (size_t)BB * HH;                 // [B,H]

    lstm_persistent<<<GRID, 256>>>(x, c0, h0, Wi, Wh, b, ys, cT, hT);
}

// round 4
// speedup vs baseline: 2.3408x; 2.3408x over previous
#include <cuda_runtime.h>
#include <cuda_bf16.h>
#include <math.h>
#include <stdint.h>

#define T_   512
#define BB   64
#define HH   1024
#define N4   4096
#define RGRID 128   // blocks in persistent recurrence kernel

// ---------------- device scratch ----------------
__device__ float         g_zx[(size_t)T_ * BB * N4];        // x@Wi + b, fp32
__device__ __nv_bfloat16 g_xhi[(size_t)T_ * BB * HH];
__device__ __nv_bfloat16 g_xlo[(size_t)T_ * BB * HH];
__device__ __nv_bfloat16 g_WiT_hi[(size_t)N4 * HH];         // [n][k]
__device__ __nv_bfloat16 g_WiT_lo[(size_t)N4 * HH];
__device__ __nv_bfloat16 g_WhT_hi[(size_t)N4 * HH];
__device__ __nv_bfloat16 g_WhT_lo[(size_t)N4 * HH];
__device__ __nv_bfloat16 g_hh_hi[2][BB * HH];               // double-buffered h
__device__ __nv_bfloat16 g_hh_lo[2][BB * HH];

// ---------------- grid barrier ----------------
__device__ unsigned int          g_bar_count = 0;
__device__ volatile unsigned int g_bar_gen   = 0;

__device__ __forceinline__ void grid_barrier()
{
    __syncthreads();
    if (threadIdx.x == 0) {
        __threadfence();
        unsigned int gen = g_bar_gen;
        if (atomicAdd(&g_bar_count, 1) == RGRID - 1) {
            g_bar_count = 0;
            __threadfence();
            g_bar_gen = gen + 1;
        } else {
            while (g_bar_gen == gen) __nanosleep(32);
        }
        __threadfence();
    }
    __syncthreads();
}

// ---------------- helpers ----------------
__device__ __forceinline__ void bsplit(float v, __nv_bfloat16& hi, __nv_bfloat16& lo)
{
    hi = __float2bfloat16(v);
    lo = __float2bfloat16(v - __bfloat162float(hi));
}

__device__ __forceinline__ void mma16816(float c[4],
                                         uint32_t a0, uint32_t a1, uint32_t a2, uint32_t a3,
                                         uint32_t b0, uint32_t b1)
{
    asm("mma.sync.aligned.m16n8k16.row.col.f32.bf16.bf16.f32 "
        "{%0,%1,%2,%3}, {%4,%5,%6,%7}, {%8,%9}, {%0,%1,%2,%3};"
        : "+f"(c[0]), "+f"(c[1]), "+f"(c[2]), "+f"(c[3])
        : "r"(a0), "r"(a1), "r"(a2), "r"(a3), "r"(b0), "r"(b1));
}

// ---------------- prep kernels ----------------
__global__ void conv_x_kernel(const float4* __restrict__ x)
{
    const int n4 = T_ * BB * HH / 4;
    __nv_bfloat162* dh = reinterpret_cast<__nv_bfloat162*>(g_xhi);
    __nv_bfloat162* dl = reinterpret_cast<__nv_bfloat162*>(g_xlo);
    for (int i = blockIdx.x * blockDim.x + threadIdx.x; i < n4;
         i += gridDim.x * blockDim.x) {
        float4 v = x[i];
        __nv_bfloat16 h0,l0,h1,l1,h2,l2,h3,l3;
        bsplit(v.x,h0,l0); bsplit(v.y,h1,l1); bsplit(v.z,h2,l2); bsplit(v.w,h3,l3);
        __nv_bfloat162 a; a.x=h0; a.y=h1; dh[2*i]   = a;
        __nv_bfloat162 b; b.x=h2; b.y=h3; dh[2*i+1] = b;
        __nv_bfloat162 c; c.x=l0; c.y=l1; dl[2*i]   = c;
        __nv_bfloat162 d; d.x=l2; d.y=l3; dl[2*i+1] = d;
    }
}

__global__ void conv_h0_kernel(const float4* __restrict__ h0)
{
    const int n4 = BB * HH / 4;
    __nv_bfloat162* dh = reinterpret_cast<__nv_bfloat162*>(g_hh_hi[0]);
    __nv_bfloat162* dl = reinterpret_cast<__nv_bfloat162*>(g_hh_lo[0]);
    for (int i = blockIdx.x * blockDim.x + threadIdx.x; i < n4;
         i += gridDim.x * blockDim.x) {
        float4 v = h0[i];
        __nv_bfloat16 a0,b0,a1,b1,a2,b2,a3,b3;
        bsplit(v.x,a0,b0); bsplit(v.y,a1,b1); bsplit(v.z,a2,b2); bsplit(v.w,a3,b3);
        __nv_bfloat162 p; p.x=a0; p.y=a1; dh[2*i]   = p;
        __nv_bfloat162 q; q.x=a2; q.y=a3; dh[2*i+1] = q;
        __nv_bfloat162 r; r.x=b0; r.y=b1; dl[2*i]   = r;
        __nv_bfloat162 s; s.x=b2; s.y=b3; dl[2*i+1] = s;
    }
}

// transpose [1024][4096] f32 -> [4096][1024] bf16 hi/lo. which: 0=Wi, 1=Wh.
__global__ void transpose_conv_kernel(const float* __restrict__ src, int which)
{
    __shared__ float tile[32][33];
    const int gx = blockIdx.x * 32;   // n
    const int gy = blockIdx.y * 32;   // k
    const int tx = threadIdx.x, ty = threadIdx.y;
#pragma unroll
    for (int i = 0; i < 4; i++) {
        int kl = ty + i * 8;
        tile[kl][tx] = src[(size_t)(gy + kl) * N4 + gx + tx];
    }
    __syncthreads();
    __nv_bfloat16* dh = which ? g_WhT_hi : g_WiT_hi;
    __nv_bfloat16* dl = which ? g_WhT_lo : g_WiT_lo;
#pragma unroll
    for (int i = 0; i < 4; i++) {
        int nl = ty + i * 8;
        float v = tile[tx][nl];
        __nv_bfloat16 h, l; bsplit(v, h, l);
        dh[(size_t)(gx + nl) * HH + gy + tx] = h;
        dl[(size_t)(gx + nl) * HH + gy + tx] = l;
    }
}

// ---------------------------------------------------------------------------
// Phase 1: g_zx = x @ Wi + b via 3x bf16 MMA. Block 128x128, 8 warps (2x4),
// warp tile 64x32. kt=32 (16 words), smem pitch 20 words (conflict-free frags).
// ---------------------------------------------------------------------------
__global__ __launch_bounds__(256) void gemm_wx_mma(const float* __restrict__ bias)
{
    __shared__ uint32_t sAh[128 * 20], sAl[128 * 20];
    __shared__ uint32_t sBh[128 * 20], sBl[128 * 20];

    const uint32_t* Xh = (const uint32_t*)g_xhi;
    const uint32_t* Xl = (const uint32_t*)g_xlo;
    const uint32_t* Wh = (const uint32_t*)g_WiT_hi;
    const uint32_t* Wl = (const uint32_t*)g_WiT_lo;

    const int tid  = threadIdx.x;
    const int bn   = blockIdx.x * 128;
    const int bm   = blockIdx.y * 128;
    const int lane = tid & 31, wp = tid >> 5;
    const int g    = lane >> 2, tq = lane & 3;
    const int wm   = (wp >> 2) * 64;
    const int wn   = (wp & 3) * 32;
    const int r0   = wp * 2 + (lane >> 4);
    const int kw   = lane & 15;

    float acc[4][4][4] = {};
    uint32_t pAh[8], pAl[8], pBh[8], pBl[8];

    auto LOAD = [&](int kc) {
        int k0w = kc * 16;
#pragma unroll
        for (int i = 0; i < 8; i++) {
            int row = r0 + 16 * i;
            size_t ga = (size_t)(bm + row) * 512 + k0w + kw;
            size_t gb = (size_t)(bn + row) * 512 + k0w + kw;
            pAh[i] = Xh[ga]; pAl[i] = Xl[ga];
            pBh[i] = Wh[gb]; pBl[i] = Wl[gb];
        }
    };
    auto STORE = [&]() {
#pragma unroll
        for (int i = 0; i < 8; i++) {
            int row = r0 + 16 * i;
            sAh[row * 20 + kw] = pAh[i]; sAl[row * 20 + kw] = pAl[i];
            sBh[row * 20 + kw] = pBh[i]; sBl[row * 20 + kw] = pBl[i];
        }
    };

    LOAD(0); STORE(); __syncthreads();

    for (int kc = 0; kc < 32; kc++) {
        if (kc < 31) LOAD(kc + 1);
#pragma unroll
        for (int s = 0; s < 2; s++) {
            int kwb = s * 8;
            uint32_t bh[4][2], bl[4][2];
#pragma unroll
            for (int nf = 0; nf < 4; nf++) {
                int base = (wn + nf * 8 + g) * 20 + kwb + tq;
                bh[nf][0] = sBh[base]; bh[nf][1] = sBh[base + 4];
                bl[nf][0] = sBl[base]; bl[nf][1] = sBl[base + 4];
            }
#pragma unroll
            for (int mf = 0; mf < 4; mf++) {
                int rb = (wm + mf * 16 + g) * 20 + kwb + tq;
                uint32_t a0 = sAh[rb], a1 = sAh[rb + 160];
                uint32_t a2 = sAh[rb + 4], a3 = sAh[rb + 164];
                uint32_t l0 = sAl[rb], l1 = sAl[rb + 160];
                uint32_t l2 = sAl[rb + 4], l3 = sAl[rb + 164];
#pragma unroll
                for (int nf = 0; nf < 4; nf++) {
                    mma16816(acc[mf][nf], a0, a1, a2, a3, bh[nf][0], bh[nf][1]);
                    mma16816(acc[mf][nf], a0, a1, a2, a3, bl[nf][0], bl[nf][1]);
                    mma16816(acc[mf][nf], l0, l1, l2, l3, bh[nf][0], bh[nf][1]);
                }
            }
        }
        __syncthreads();
        if (kc < 31) { STORE(); __syncthreads(); }
    }

#pragma unroll
    for (int mf = 0; mf < 4; mf++) {
        int row0 = bm + wm + mf * 16 + g;
#pragma unroll
        for (int nf = 0; nf < 4; nf++) {
            int col = bn + wn + nf * 8 + tq * 2;
            float2 bb = *(const float2*)&bias[col];
            float2 v0, v1;
            v0.x = acc[mf][nf][0] + bb.x; v0.y = acc[mf][nf][1] + bb.y;
            v1.x = acc[mf][nf][2] + bb.x; v1.y = acc[mf][nf][3] + bb.y;
            *(float2*)&g_zx[(size_t)row0 * N4 + col]       = v0;
            *(float2*)&g_zx[(size_t)(row0 + 8) * N4 + col] = v1;
        }
    }
}

// ---------------------------------------------------------------------------
// Persistent recurrence: 128 blocks, block owns 8 h-columns x 4 gates
// (32 effective cols), M=64, K=1024. 3x bf16 MMA; pitch 36 words.
// ---------------------------------------------------------------------------
__global__ __launch_bounds__(256, 1)
void lstm_rec_mma(const float* __restrict__ c0,
                  float* __restrict__ ys,
                  float* __restrict__ cT,
                  float* __restrict__ hT)
{
    __shared__ uint32_t sAh[64 * 36], sAl[64 * 36];
    __shared__ uint32_t sBh[32 * 36], sBl[32 * 36];
    __shared__ float Z[64][33];

    const int tid  = threadIdx.x, bid = blockIdx.x;
    const int lane = tid & 31, wp = tid >> 5;
    const int g    = lane >> 2, tq = lane & 3;
    const int mrow = (wp & 3) * 16;
    const int nb0  = (wp >> 2) * 16;
    const int jb   = bid * 8;

    const uint32_t* WhH = (const uint32_t*)g_WhT_hi;
    const uint32_t* WhL = (const uint32_t*)g_WhT_lo;

    size_t bOff[4];
#pragma unroll
    for (int i = 0; i < 4; i++) {
        int e = wp * 4 + i;
        bOff[i] = ((size_t)((e >> 3) * 1024 + jb + (e & 7))) * 512;
    }

    for (int t = 0; t < T_; t++) {
        const uint32_t* Hh = (const uint32_t*)g_hh_hi[t & 1];
        const uint32_t* Hl = (const uint32_t*)g_hh_lo[t & 1];

        float acc[2][4] = {};
        uint32_t pAh[8], pAl[8], pBh[4], pBl[4];

        auto LOAD = [&](int kc) {
            int k0w = kc * 32;
#pragma unroll
            for (int i = 0; i < 8; i++) {
                int row = wp + 8 * i;
                size_t a = (size_t)row * 512 + k0w + lane;
                pAh[i] = Hh[a]; pAl[i] = Hl[a];
            }
#pragma unroll
            for (int i = 0; i < 4; i++) {
                size_t a = bOff[i] + k0w + lane;
                pBh[i] = WhH[a]; pBl[i] = WhL[a];
            }
        };
        auto STORE = [&]() {
#pragma unroll
            for (int i = 0; i < 8; i++) {
                int row = wp + 8 * i;
                sAh[row * 36 + lane] = pAh[i];
                sAl[row * 36 + lane] = pAl[i];
            }
#pragma unroll
            for (int i = 0; i < 4; i++) {
                int e = wp * 4 + i;
                sBh[e * 36 + lane] = pBh[i];
                sBl[e * 36 + lane] = pBl[i];
            }
        };

        LOAD(0); STORE(); __syncthreads();

        for (int kc = 0; kc < 16; kc++) {
            if (kc < 15) LOAD(kc + 1);
#pragma unroll
            for (int s = 0; s < 4; s++) {
                int kwb = s * 8;
                uint32_t bh[2][2], bl[2][2];
#pragma unroll
                for (int j = 0; j < 2; j++) {
                    int base = (nb0 + j * 8 + g) * 36 + kwb + tq;
                    bh[j][0] = sBh[base]; bh[j][1] = sBh[base + 4];
                    bl[j][0] = sBl[base]; bl[j][1] = sBl[base + 4];
                }
                int rb = (mrow + g) * 36 + kwb + tq;
                uint32_t a0 = sAh[rb], a1 = sAh[rb + 288];
                uint32_t a2 = sAh[rb + 4], a3 = sAh[rb + 292];
                uint32_t l0 = sAl[rb], l1 = sAl[rb + 288];
                uint32_t l2 = sAl[rb + 4], l3 = sAl[rb + 292];
#pragma unroll
                for (int j = 0; j < 2; j++) {
                    mma16816(acc[j], a0, a1, a2, a3, bh[j][0], bh[j][1]);
                    mma16816(acc[j], a0, a1, a2, a3, bl[j][0], bl[j][1]);
                    mma16816(acc[j], l0, l1, l2, l3, bh[j][0], bh[j][1]);
                }
            }
            __syncthreads();
            if (kc < 15) { STORE(); __syncthreads(); }
        }

        // stage z tile
#pragma unroll
        for (int j = 0; j < 2; j++) {
            int e0 = nb0 + j * 8 + tq * 2;
            Z[mrow + g][e0]         = acc[j][0];
            Z[mrow + g][e0 + 1]     = acc[j][1];
            Z[mrow + g + 8][e0]     = acc[j][2];
            Z[mrow + g + 8][e0 + 1] = acc[j][3];
        }
        __syncthreads();

        // pointwise gates
        const float* zx = g_zx + (size_t)t * BB * N4;
        const float* cp = (t == 0) ? c0 : cT;
        float* ys_t = ys + (size_t)t * BB * HH;
        __nv_bfloat16* nhh = g_hh_hi[(t + 1) & 1];
        __nv_bfloat16* nhl = g_hh_lo[(t + 1) & 1];

#pragma unroll
        for (int p = 0; p < 2; p++) {
            int pe = tid * 2 + p;
            int b_ = pe >> 3, jj = pe & 7, j = jb + jj;
            size_t zb = (size_t)b_ * N4;

            float zi = Z[b_][jj]      + zx[zb + j];
            float zf = Z[b_][8 + jj]  + zx[zb + HH + j];
            float zg = Z[b_][16 + jj] + zx[zb + 2 * HH + j];
            float zo = Z[b_][24 + jj] + zx[zb + 3 * HH + j];

            float ig = 1.f / (1.f + expf(-zi));
            float fg = 1.f / (1.f + expf(-zf));
            float gg = tanhf(zg);
            float og = 1.f / (1.f + expf(-zo));

            float cc = fg * cp[(size_t)b_ * HH + j] + ig * gg;
            float hh = og * tanhf(cc);

            cT[(size_t)b_ * HH + j]   = cc;
            ys_t[(size_t)b_ * HH + j] = hh;
            __nv_bfloat16 hb, lb; bsplit(hh, hb, lb);
            nhh[b_ * HH + j] = hb;
            nhl[b_ * HH + j] = lb;
            if (t == T_ - 1) hT[(size_t)b_ * HH + j] = hh;
        }

        grid_barrier();
    }
}

// ---------------------------------------------------------------------------
extern "C" void kernel_launch(void* const* d_in, const int* in_sizes, int n_in,
                              void* d_out, int out_size)
{
    const float* x  = (const float*)d_in[0];   // [T,B,D]
    const float* c0 = (const float*)d_in[1];   // [B,H]
    const float* h0 = (const float*)d_in[2];   // [B,H]
    const float* Wi = (const float*)d_in[3];   // [D,4H]
    const float* Wh = (const float*)d_in[4];   // [H,4H]
    const float* b  = (const float*)d_in[5];   // [4H]

    float* out = (float*)d_out;
    float* ys = out;                                  // [T,B,H]
    float* cT = out + (size_t)T_ * BB * HH;           // [B,H]
    float* hT = cT + (size_t)BB * HH;                 // [B,H]

    conv_x_kernel<<<4096, 256>>>((const float4*)x);
    conv_h0_kernel<<<64, 256>>>((const float4*)h0);
    dim3 tb(32, 8);
    transpose_conv_kernel<<<dim3(128, 32), tb>>>(Wi, 0);
    transpose_conv_kernel<<<dim3(128, 32), tb>>>(Wh, 1);

    gemm_wx_mma<<<dim3(32, 256), 256>>>(b);

    lstm_rec_mma<<<RGRID, 256>>>(c0, ys, cT, hT);
}

// round 5
// speedup vs baseline: 2.7179x; 1.1611x over previous
#include <cuda_runtime.h>
#include <cuda_bf16.h>
#include <math.h>
#include <stdint.h>

#define T_   512
#define BB   64
#define HH   1024
#define N4   4096
#define RGRID 128   // blocks in persistent recurrence kernel

// ---------------- device scratch ----------------
__device__ float         g_zx[(size_t)T_ * BB * N4];        // x@Wi + b, fp32
__device__ __nv_bfloat16 g_xhi[(size_t)T_ * BB * HH];
__device__ __nv_bfloat16 g_xlo[(size_t)T_ * BB * HH];
__device__ __nv_bfloat16 g_WiT_hi[(size_t)N4 * HH];         // [n][k]
__device__ __nv_bfloat16 g_WiT_lo[(size_t)N4 * HH];
__device__ __nv_bfloat16 g_WhT_hi[(size_t)N4 * HH];         // [n][k] (pack source)
__device__ __nv_bfloat16 g_WhT_lo[(size_t)N4 * HH];

// Fragment-order operands for the recurrence MMA (no smem staging):
// A (h): [buf 2][m(4)][kc(64)][lane(32)] uint4  (2048 uint4 per m)
__device__ uint4 g_hfrag_hi[2][4 * 64 * 32];
__device__ uint4 g_hfrag_lo[2][4 * 64 * 32];
// B (Wh): [bid(128)][nhalf(2)][kc(64)][lane(32)] uint4
__device__ uint4 g_whfrag_hi[(size_t)128 * 2 * 64 * 32];
__device__ uint4 g_whfrag_lo[(size_t)128 * 2 * 64 * 32];

// ---------------- grid barrier ----------------
__device__ unsigned int          g_bar_count = 0;
__device__ volatile unsigned int g_bar_gen   = 0;

__device__ __forceinline__ void grid_barrier()
{
    __syncthreads();
    if (threadIdx.x == 0) {
        __threadfence();
        unsigned int gen = g_bar_gen;
        if (atomicAdd(&g_bar_count, 1) == RGRID - 1) {
            g_bar_count = 0;
            __threadfence();
            g_bar_gen = gen + 1;
        } else {
            while (g_bar_gen == gen) __nanosleep(32);
        }
        __threadfence();
    }
    __syncthreads();
}

// ---------------- helpers ----------------
__device__ __forceinline__ void bsplit(float v, __nv_bfloat16& hi, __nv_bfloat16& lo)
{
    hi = __float2bfloat16(v);
    lo = __float2bfloat16(v - __bfloat162float(hi));
}

__device__ __forceinline__ void mma16816(float c[4],
                                         uint32_t a0, uint32_t a1, uint32_t a2, uint32_t a3,
                                         uint32_t b0, uint32_t b1)
{
    asm("mma.sync.aligned.m16n8k16.row.col.f32.bf16.bf16.f32 "
        "{%0,%1,%2,%3}, {%4,%5,%6,%7}, {%8,%9}, {%0,%1,%2,%3};"
        : "+f"(c[0]), "+f"(c[1]), "+f"(c[2]), "+f"(c[3])
        : "r"(a0), "r"(a1), "r"(a2), "r"(a3), "r"(b0), "r"(b1));
}

// ---------------- prep kernels ----------------
__global__ void conv_x_kernel(const float4* __restrict__ x)
{
    const int n4 = T_ * BB * HH / 4;
    __nv_bfloat162* dh = reinterpret_cast<__nv_bfloat162*>(g_xhi);
    __nv_bfloat162* dl = reinterpret_cast<__nv_bfloat162*>(g_xlo);
    for (int i = blockIdx.x * blockDim.x + threadIdx.x; i < n4;
         i += gridDim.x * blockDim.x) {
        float4 v = x[i];
        __nv_bfloat16 h0,l0,h1,l1,h2,l2,h3,l3;
        bsplit(v.x,h0,l0); bsplit(v.y,h1,l1); bsplit(v.z,h2,l2); bsplit(v.w,h3,l3);
        __nv_bfloat162 a; a.x=h0; a.y=h1; dh[2*i]   = a;
        __nv_bfloat162 b; b.x=h2; b.y=h3; dh[2*i+1] = b;
        __nv_bfloat162 c; c.x=l0; c.y=l1; dl[2*i]   = c;
        __nv_bfloat162 d; d.x=l2; d.y=l3; dl[2*i+1] = d;
    }
}

// h0 -> fragment-order buffer 0
__global__ void conv_h0_frag(const float* __restrict__ h0)
{
    int idx = blockIdx.x * blockDim.x + threadIdx.x;    // 0 .. 64*512-1
    if (idx >= BB * 512) return;
    int b_ = idx >> 9;          // batch row
    int p  = idx & 511;         // k-pair index
    float v0 = h0[b_ * HH + 2 * p];
    float v1 = h0[b_ * HH + 2 * p + 1];
    __nv_bfloat16 h0b,l0b,h1b,l1b;
    bsplit(v0,h0b,l0b); bsplit(v1,h1b,l1b);
    __nv_bfloat162 wh; wh.x=h0b; wh.y=h1b;
    __nv_bfloat162 wl; wl.x=l0b; wl.y=l1b;

    int kc = p >> 3, within = p & 7;
    int tq = within & 3, whi = within >> 2;
    int m = b_ >> 4, r16 = b_ & 15;
    int gq = r16 & 7, top = r16 >> 3;
    int lane = gq * 4 + tq;
    int w = whi * 2 + top;
    uint32_t off = (uint32_t)(((m * 64 + kc) * 32 + lane) * 4 + w);
    ((uint32_t*)g_hfrag_hi[0])[off] = *(uint32_t*)&wh;
    ((uint32_t*)g_hfrag_lo[0])[off] = *(uint32_t*)&wl;
}

// transpose [1024][4096] f32 -> [4096][1024] bf16 hi/lo. which: 0=Wi, 1=Wh.
__global__ void transpose_conv_kernel(const float* __restrict__ src, int which)
{
    __shared__ float tile[32][33];
    const int gx = blockIdx.x * 32;   // n
    const int gy = blockIdx.y * 32;   // k
    const int tx = threadIdx.x, ty = threadIdx.y;
#pragma unroll
    for (int i = 0; i < 4; i++) {
        int kl = ty + i * 8;
        tile[kl][tx] = src[(size_t)(gy + kl) * N4 + gx + tx];
    }
    __syncthreads();
    __nv_bfloat16* dh = which ? g_WhT_hi : g_WiT_hi;
    __nv_bfloat16* dl = which ? g_WhT_lo : g_WiT_lo;
#pragma unroll
    for (int i = 0; i < 4; i++) {
        int nl = ty + i * 8;
        float v = tile[tx][nl];
        __nv_bfloat16 h, l; bsplit(v, h, l);
        dh[(size_t)(gx + nl) * HH + gy + tx] = h;
        dl[(size_t)(gx + nl) * HH + gy + tx] = l;
    }
}

// Pack WhT (k-major per col) into per-thread MMA B-fragment order.
__global__ void whfrag_pack()
{
    int widx = blockIdx.x * blockDim.x + threadIdx.x;   // 0 .. 524287
    if (widx >= 128 * 2 * 64 * 32) return;
    int lane  = widx & 31;
    int kc    = (widx >> 5) & 63;
    int nhalf = (widx >> 11) & 1;
    int bidn  = widx >> 12;
    int gq = lane >> 2, tq = lane & 3;

    const uint32_t* WH = (const uint32_t*)g_WhT_hi;   // [col][512 pairs]
    const uint32_t* WL = (const uint32_t*)g_WhT_lo;
    uint32_t hi[4], lo[4];
#pragma unroll
    for (int w = 0; w < 4; w++) {
        int j = w >> 1, b = w & 1;
        int zc = nhalf * 16 + j * 8 + gq;             // 0..31
        int col = (zc >> 3) * 1024 + bidn * 8 + (zc & 7);
        int pair = kc * 8 + tq + b * 4;
        hi[w] = WH[(size_t)col * 512 + pair];
        lo[w] = WL[(size_t)col * 512 + pair];
    }
    g_whfrag_hi[widx] = make_uint4(hi[0], hi[1], hi[2], hi[3]);
    g_whfrag_lo[widx] = make_uint4(lo[0], lo[1], lo[2], lo[3]);
}

// ---------------------------------------------------------------------------
// Phase 1: g_zx = x @ Wi + b via 3x bf16 MMA. Block 128x128, 8 warps (2x4),
// warp tile 64x32. kt=32 (16 words), smem pitch 20 words (conflict-free frags).
// ---------------------------------------------------------------------------
__global__ __launch_bounds__(256) void gemm_wx_mma(const float* __restrict__ bias)
{
    __shared__ uint32_t sAh[128 * 20], sAl[128 * 20];
    __shared__ uint32_t sBh[128 * 20], sBl[128 * 20];

    const uint32_t* Xh = (const uint32_t*)g_xhi;
    const uint32_t* Xl = (const uint32_t*)g_xlo;
    const uint32_t* Wh = (const uint32_t*)g_WiT_hi;
    const uint32_t* Wl = (const uint32_t*)g_WiT_lo;

    const int tid  = threadIdx.x;
    const int bn   = blockIdx.x * 128;
    const int bm   = blockIdx.y * 128;
    const int lane = tid & 31, wp = tid >> 5;
    const int g    = lane >> 2, tq = lane & 3;
    const int wm   = (wp >> 2) * 64;
    const int wn   = (wp & 3) * 32;
    const int r0   = wp * 2 + (lane >> 4);
    const int kw   = lane & 15;

    float acc[4][4][4] = {};
    uint32_t pAh[8], pAl[8], pBh[8], pBl[8];

    auto LOAD = [&](int kc) {
        int k0w = kc * 16;
#pragma unroll
        for (int i = 0; i < 8; i++) {
            int row = r0 + 16 * i;
            size_t ga = (size_t)(bm + row) * 512 + k0w + kw;
            size_t gb = (size_t)(bn + row) * 512 + k0w + kw;
            pAh[i] = Xh[ga]; pAl[i] = Xl[ga];
            pBh[i] = Wh[gb]; pBl[i] = Wl[gb];
        }
    };
    auto STORE = [&]() {
#pragma unroll
        for (int i = 0; i < 8; i++) {
            int row = r0 + 16 * i;
            sAh[row * 20 + kw] = pAh[i]; sAl[row * 20 + kw] = pAl[i];
            sBh[row * 20 + kw] = pBh[i]; sBl[row * 20 + kw] = pBl[i];
        }
    };

    LOAD(0); STORE(); __syncthreads();

    for (int kc = 0; kc < 32; kc++) {
        if (kc < 31) LOAD(kc + 1);
#pragma unroll
        for (int s = 0; s < 2; s++) {
            int kwb = s * 8;
            uint32_t bh[4][2], bl[4][2];
#pragma unroll
            for (int nf = 0; nf < 4; nf++) {
                int base = (wn + nf * 8 + g) * 20 + kwb + tq;
                bh[nf][0] = sBh[base]; bh[nf][1] = sBh[base + 4];
                bl[nf][0] = sBl[base]; bl[nf][1] = sBl[base + 4];
            }
#pragma unroll
            for (int mf = 0; mf < 4; mf++) {
                int rb = (wm + mf * 16 + g) * 20 + kwb + tq;
                uint32_t a0 = sAh[rb], a1 = sAh[rb + 160];
                uint32_t a2 = sAh[rb + 4], a3 = sAh[rb + 164];
                uint32_t l0 = sAl[rb], l1 = sAl[rb + 160];
                uint32_t l2 = sAl[rb + 4], l3 = sAl[rb + 164];
#pragma unroll
                for (int nf = 0; nf < 4; nf++) {
                    mma16816(acc[mf][nf], a0, a1, a2, a3, bh[nf][0], bh[nf][1]);
                    mma16816(acc[mf][nf], a0, a1, a2, a3, bl[nf][0], bl[nf][1]);
                    mma16816(acc[mf][nf], l0, l1, l2, l3, bh[nf][0], bh[nf][1]);
                }
            }
        }
        __syncthreads();
        if (kc < 31) { STORE(); __syncthreads(); }
    }

#pragma unroll
    for (int mf = 0; mf < 4; mf++) {
        int row0 = bm + wm + mf * 16 + g;
#pragma unroll
        for (int nf = 0; nf < 4; nf++) {
            int col = bn + wn + nf * 8 + tq * 2;
            float2 bb = *(const float2*)&bias[col];
            float2 v0, v1;
            v0.x = acc[mf][nf][0] + bb.x; v0.y = acc[mf][nf][1] + bb.y;
            v1.x = acc[mf][nf][2] + bb.x; v1.y = acc[mf][nf][3] + bb.y;
            *(float2*)&g_zx[(size_t)row0 * N4 + col]       = v0;
            *(float2*)&g_zx[(size_t)(row0 + 8) * N4 + col] = v1;
        }
    }
}

// ---------------------------------------------------------------------------
// Persistent recurrence: 128 blocks x 256 thr. Block owns 8 h-cols (32 z-cols).
// MMA operands streamed from fragment-order global arrays, no smem staging.
// Per warp: m16 x n16 (2 n8 frags). K loop: 64 chunks of k16.
// ---------------------------------------------------------------------------
__global__ __launch_bounds__(256, 1)
void lstm_rec_mma(const float* __restrict__ c0,
                  float* __restrict__ ys,
                  float* __restrict__ cT,
                  float* __restrict__ hT)
{
    __shared__ float Z[64][33];

    const int tid  = threadIdx.x, bid = blockIdx.x;
    const int lane = tid & 31, wp = tid >> 5;
    const int gq   = lane >> 2, tq = lane & 3;
    const int m    = wp & 3;            // m16 block (rows m*16..+15)
    const int nhalf= wp >> 2;           // n16 half (z-cols nhalf*16..+15)
    const int jb   = bid * 8;

    const uint4* WBh = g_whfrag_hi + ((size_t)(bid * 2 + nhalf) * 64) * 32;
    const uint4* WBl = g_whfrag_lo + ((size_t)(bid * 2 + nhalf) * 64) * 32;

    // pointwise decode (thread -> (batch row, col pair))
    const int pb  = tid >> 2;           // 0..63
    const int jj  = (tid & 3) * 2;      // 0,2,4,6
    const int j0  = jb + jj;
    // h-frag store address for this thread's pair
    const int p_g   = j0 >> 1;
    const int kcw   = p_g >> 3, within = p_g & 7;
    const int ptq   = within & 3, pwhi = within >> 2;
    const int pm    = pb >> 4, r16 = pb & 15;
    const int pg    = r16 & 7, ptop = r16 >> 3;
    const uint32_t hoff = (uint32_t)((((pm * 64 + kcw) * 32) + pg * 4 + ptq) * 4
                                     + pwhi * 2 + ptop);

    for (int t = 0; t < T_; t++) {
        const uint4* AH = g_hfrag_hi[t & 1] + m * 2048;
        const uint4* AL = g_hfrag_lo[t & 1] + m * 2048;

        float acc0[4] = {}, acc1[4] = {};
        uint4 sAh[4], sAl[4], sBh[4], sBl[4];

#pragma unroll
        for (int s = 0; s < 4; s++) {
            sAh[s] = AH[s * 32 + lane];  sAl[s] = AL[s * 32 + lane];
            sBh[s] = WBh[s * 32 + lane]; sBl[s] = WBl[s * 32 + lane];
        }

#pragma unroll 4
        for (int kc = 0; kc < 64; kc++) {
            int cur = kc & 3;
            uint4 ah = sAh[cur], al = sAl[cur];
            uint4 bh = sBh[cur], bl = sBl[cur];
            if (kc + 4 < 64) {
                int nx = (kc + 4) * 32 + lane;
                sAh[cur] = AH[nx];  sAl[cur] = AL[nx];
                sBh[cur] = WBh[nx]; sBl[cur] = WBl[nx];
            }
            // j = 0 (n8 low): b words (x=tq, y=tq+4)
            mma16816(acc0, ah.x, ah.y, ah.z, ah.w, bh.x, bh.y);
            mma16816(acc0, ah.x, ah.y, ah.z, ah.w, bl.x, bl.y);
            mma16816(acc0, al.x, al.y, al.z, al.w, bh.x, bh.y);
            // j = 1 (n8 high)
            mma16816(acc1, ah.x, ah.y, ah.z, ah.w, bh.z, bh.w);
            mma16816(acc1, ah.x, ah.y, ah.z, ah.w, bl.z, bl.w);
            mma16816(acc1, al.x, al.y, al.z, al.w, bh.z, bh.w);
        }

        // stage z tile (warp-private acc -> smem)
        {
            int mrow = m * 16, nb0 = nhalf * 16;
            int e0 = nb0 + tq * 2;
            Z[mrow + gq][e0]          = acc0[0];
            Z[mrow + gq][e0 + 1]      = acc0[1];
            Z[mrow + gq + 8][e0]      = acc0[2];
            Z[mrow + gq + 8][e0 + 1]  = acc0[3];
            int e1 = nb0 + 8 + tq * 2;
            Z[mrow + gq][e1]          = acc1[0];
            Z[mrow + gq][e1 + 1]      = acc1[1];
            Z[mrow + gq + 8][e1]      = acc1[2];
            Z[mrow + gq + 8][e1 + 1]  = acc1[3];
        }
        __syncthreads();

        // pointwise gates: 2 elements (pb, j0) and (pb, j0+1)
        {
            const float* zx = g_zx + (size_t)t * BB * N4 + (size_t)pb * N4;
            const float* cp = (t == 0) ? c0 : cT;
            float* ys_t = ys + (size_t)t * BB * HH;
            uint32_t* nhh = (uint32_t*)g_hfrag_hi[(t + 1) & 1];
            uint32_t* nhl = (uint32_t*)g_hfrag_lo[(t + 1) & 1];

            float2 xi = *(const float2*)&zx[j0];
            float2 xf = *(const float2*)&zx[HH + j0];
            float2 xg = *(const float2*)&zx[2 * HH + j0];
            float2 xo = *(const float2*)&zx[3 * HH + j0];
            float2 cv = *(const float2*)&cp[(size_t)pb * HH + j0];

            float h2[2], c2[2];
#pragma unroll
            for (int e = 0; e < 2; e++) {
                int zc = jj + e;
                float zi = Z[pb][zc]      + (e ? xi.y : xi.x);
                float zf = Z[pb][8 + zc]  + (e ? xf.y : xf.x);
                float zg = Z[pb][16 + zc] + (e ? xg.y : xg.x);
                float zo = Z[pb][24 + zc] + (e ? xo.y : xo.x);

                float ig = 1.f / (1.f + expf(-zi));
                float fg = 1.f / (1.f + expf(-zf));
                float gg = tanhf(zg);
                float og = 1.f / (1.f + expf(-zo));

                float cc = fg * (e ? cv.y : cv.x) + ig * gg;
                c2[e] = cc;
                h2[e] = og * tanhf(cc);
            }

            *(float2*)&cT[(size_t)pb * HH + j0]   = *(float2*)c2;
            *(float2*)&ys_t[(size_t)pb * HH + j0] = *(float2*)h2;
            if (t == T_ - 1) *(float2*)&hT[(size_t)pb * HH + j0] = *(float2*)h2;

            __nv_bfloat16 h0b,l0b,h1b,l1b;
            bsplit(h2[0], h0b, l0b); bsplit(h2[1], h1b, l1b);
            __nv_bfloat162 wh; wh.x = h0b; wh.y = h1b;
            __nv_bfloat162 wl; wl.x = l0b; wl.y = l1b;
            nhh[hoff] = *(uint32_t*)&wh;
            nhl[hoff] = *(uint32_t*)&wl;
        }

        grid_barrier();
    }
}

// ---------------------------------------------------------------------------
extern "C" void kernel_launch(void* const* d_in, const int* in_sizes, int n_in,
                              void* d_out, int out_size)
{
    const float* x  = (const float*)d_in[0];   // [T,B,D]
    const float* c0 = (const float*)d_in[1];   // [B,H]
    const float* h0 = (const float*)d_in[2];   // [B,H]
    const float* Wi = (const float*)d_in[3];   // [D,4H]
    const float* Wh = (const float*)d_in[4];   // [H,4H]
    const float* b  = (const float*)d_in[5];   // [4H]

    float* out = (float*)d_out;
    float* ys = out;                                  // [T,B,H]
    float* cT = out + (size_t)T_ * BB * HH;           // [B,H]
    float* hT = cT + (size_t)BB * HH;                 // [B,H]

    conv_x_kernel<<<4096, 256>>>((const float4*)x);
    conv_h0_frag<<<128, 256>>>(h0);
    dim3 tb(32, 8);
    transpose_conv_kernel<<<dim3(128, 32), tb>>>(Wi, 0);
    transpose_conv_kernel<<<dim3(128, 32), tb>>>(Wh, 1);
    whfrag_pack<<<2048, 256>>>();

    gemm_wx_mma<<<dim3(32, 256), 256>>>(b);

    lstm_rec_mma<<<RGRID, 256>>>(c0, ys, cT, hT);
}

// round 7
// speedup vs baseline: 3.2572x; 1.1984x over previous
#include <cuda_runtime.h>
#include <cuda_bf16.h>
#include <math.h>
#include <stdint.h>

#define T_   512
#define BB   64
#define HH   1024
#define N4   4096
#define RGRID 128   // blocks in persistent recurrence kernel

// ---------------- device scratch ----------------
__device__ float         g_zx[(size_t)T_ * BB * N4];        // x@Wi + b, fp32
__device__ __nv_bfloat16 g_xhi[(size_t)T_ * BB * HH];
__device__ __nv_bfloat16 g_xlo[(size_t)T_ * BB * HH];
__device__ __nv_bfloat16 g_WiT_hi[(size_t)N4 * HH];         // [n][k]
__device__ __nv_bfloat16 g_WiT_lo[(size_t)N4 * HH];
__device__ __nv_bfloat16 g_WhT_hi[(size_t)N4 * HH];         // [n][k] (pack source)
__device__ __nv_bfloat16 g_WhT_lo[(size_t)N4 * HH];

// Fragment-order operands for the recurrence MMA (no smem staging):
// A (h): [buf 2][m(4)][kc(64)][lane(32)] uint4
__device__ uint4 g_hfrag_hi[2][4 * 64 * 32];
__device__ uint4 g_hfrag_lo[2][4 * 64 * 32];
// B (Wh): [bid(128)][nhalf(2)][kc(64)][lane(32)] uint4
__device__ uint4 g_whfrag_hi[(size_t)128 * 2 * 64 * 32];
__device__ uint4 g_whfrag_lo[(size_t)128 * 2 * 64 * 32];

// ---------------- grid barrier ----------------
__device__ unsigned int          g_bar_count = 0;
__device__ volatile unsigned int g_bar_gen   = 0;

__device__ __forceinline__ void grid_barrier()
{
    __syncthreads();
    if (threadIdx.x == 0) {
        __threadfence();
        unsigned int gen = g_bar_gen;
        if (atomicAdd(&g_bar_count, 1) == RGRID - 1) {
            g_bar_count = 0;
            __threadfence();
            g_bar_gen = gen + 1;
        } else {
            while (g_bar_gen == gen) __nanosleep(32);
        }
        __threadfence();
    }
    __syncthreads();
}

// ---------------- helpers ----------------
__device__ __forceinline__ void bsplit(float v, __nv_bfloat16& hi, __nv_bfloat16& lo)
{
    hi = __float2bfloat16(v);
    lo = __float2bfloat16(v - __bfloat162float(hi));
}

__device__ __forceinline__ float fast_sigmoid(float x)
{
    return __frcp_rn(1.f + __expf(-x));
}
__device__ __forceinline__ float fast_tanh(float x)
{
    // tanh(x) = 1 - 2/(exp(2x)+1)
    return 1.f - 2.f * __frcp_rn(__expf(2.f * x) + 1.f);
}

__device__ __forceinline__ void mma16816(float c[4],
                                         uint32_t a0, uint32_t a1, uint32_t a2, uint32_t a3,
                                         uint32_t b0, uint32_t b1)
{
    asm("mma.sync.aligned.m16n8k16.row.col.f32.bf16.bf16.f32 "
        "{%0,%1,%2,%3}, {%4,%5,%6,%7}, {%8,%9}, {%0,%1,%2,%3};"
        : "+f"(c[0]), "+f"(c[1]), "+f"(c[2]), "+f"(c[3])
        : "r"(a0), "r"(a1), "r"(a2), "r"(a3), "r"(b0), "r"(b1));
}

// ---------------------------------------------------------------------------
// Fused prep kernel (launch 1). Sections by blockIdx.x:
//  [0, 8192)        : split-convert x -> g_xhi/g_xlo  (4 float4 per thread)
//  [8192, 12288)    : transpose+split Wi -> g_WiT_hi/lo
//  [12288, 16384)   : transpose+split Wh -> g_WhT_hi/lo
//  [16384, 16512)   : h0 -> fragment buffer 0
// ---------------------------------------------------------------------------
__global__ __launch_bounds__(256) void prep_fused(const float* __restrict__ x,
                                                  const float* __restrict__ Wi,
                                                  const float* __restrict__ Wh,
                                                  const float* __restrict__ h0)
{
    const int blk = blockIdx.x;
    const int tid = threadIdx.x;

    if (blk < 8192) {
        // ---- conv x : 8,388,608 float4 total = 8192 blk * 256 thr * 4 ----
        const float4* xv = (const float4*)x;
        __nv_bfloat162* dh = reinterpret_cast<__nv_bfloat162*>(g_xhi);
        __nv_bfloat162* dl = reinterpret_cast<__nv_bfloat162*>(g_xlo);
#pragma unroll
        for (int j = 0; j < 4; j++) {
            int i = blk * 256 + tid + j * (8192 * 256);
            float4 v = xv[i];
            __nv_bfloat16 h0b,l0b,h1b,l1b,h2b,l2b,h3b,l3b;
            bsplit(v.x,h0b,l0b); bsplit(v.y,h1b,l1b);
            bsplit(v.z,h2b,l2b); bsplit(v.w,h3b,l3b);
            __nv_bfloat162 a; a.x=h0b; a.y=h1b; dh[2*i]   = a;
            __nv_bfloat162 b; b.x=h2b; b.y=h3b; dh[2*i+1] = b;
            __nv_bfloat162 c; c.x=l0b; c.y=l1b; dl[2*i]   = c;
            __nv_bfloat162 d; d.x=l2b; d.y=l3b; dl[2*i+1] = d;
        }
    } else if (blk < 16384) {
        // ---- transpose + split (Wi or Wh) ----
        __shared__ float tile[32][33];
        int which = (blk >= 12288);
        int tt = blk - (which ? 12288 : 8192);           // 0..4095
        const float* src = which ? Wh : Wi;
        int gx = (tt & 127) * 32;                        // n
        int gy = (tt >> 7) * 32;                         // k
#pragma unroll
        for (int i = 0; i < 4; i++) {
            int idx = tid + i * 256;
            int kl = idx >> 5, col = idx & 31;
            tile[kl][col] = src[(size_t)(gy + kl) * N4 + gx + col];
        }
        __syncthreads();
        __nv_bfloat16* dh = which ? g_WhT_hi : g_WiT_hi;
        __nv_bfloat16* dl = which ? g_WhT_lo : g_WiT_lo;
#pragma unroll
        for (int i = 0; i < 4; i++) {
            int idx = tid + i * 256;
            int nl = idx >> 5, kc = idx & 31;
            float v = tile[kc][nl];
            __nv_bfloat16 h, l; bsplit(v, h, l);
            dh[(size_t)(gx + nl) * HH + gy + kc] = h;
            dl[(size_t)(gx + nl) * HH + gy + kc] = l;
        }
    } else {
        // ---- h0 -> fragment buffer 0 ----
        int idx = (blk - 16384) * 256 + tid;             // 0 .. 64*512-1
        int b_ = idx >> 9;
        int p  = idx & 511;
        float v0 = h0[b_ * HH + 2 * p];
        float v1 = h0[b_ * HH + 2 * p + 1];
        __nv_bfloat16 h0b,l0b,h1b,l1b;
        bsplit(v0,h0b,l0b); bsplit(v1,h1b,l1b);
        __nv_bfloat162 wh; wh.x=h0b; wh.y=h1b;
        __nv_bfloat162 wl; wl.x=l0b; wl.y=l1b;

        int kc = p >> 3, within = p & 7;
        int tq = within & 3, whi = within >> 2;
        int m = b_ >> 4, r16 = b_ & 15;
        int gq = r16 & 7, top = r16 >> 3;
        int lane = gq * 4 + tq;
        int w = whi * 2 + top;
        uint32_t off = (uint32_t)(((m * 64 + kc) * 32 + lane) * 4 + w);
        ((uint32_t*)g_hfrag_hi[0])[off] = *(uint32_t*)&wh;
        ((uint32_t*)g_hfrag_lo[0])[off] = *(uint32_t*)&wl;
    }
}

// ---------------------------------------------------------------------------
// Launch 2 (fused): blocks [0,8192) = phase-1 GEMM tiles; [8192,10240) = Wh
// fragment pack (reads g_WhT written by launch 1).
// ---------------------------------------------------------------------------
__global__ __launch_bounds__(256) void gemm_wx_pack(const float* __restrict__ bias)
{
    const int blk = blockIdx.x;
    const int tid = threadIdx.x;

    if (blk >= 8192) {
        // ---- Wh fragment pack ----
        int widx = (blk - 8192) * 256 + tid;             // 0 .. 524287
        int lane  = widx & 31;
        int kc    = (widx >> 5) & 63;
        int nhalf = (widx >> 11) & 1;
        int bidn  = widx >> 12;
        int gq = lane >> 2, tq = lane & 3;

        const uint32_t* WH = (const uint32_t*)g_WhT_hi;  // [col][512 pairs]
        const uint32_t* WL = (const uint32_t*)g_WhT_lo;
        uint32_t hi[4], lo[4];
#pragma unroll
        for (int w = 0; w < 4; w++) {
            int j = w >> 1, b = w & 1;
            int zc = nhalf * 16 + j * 8 + gq;
            int col = (zc >> 3) * 1024 + bidn * 8 + (zc & 7);
            int pair = kc * 8 + tq + b * 4;
            hi[w] = WH[(size_t)col * 512 + pair];
            lo[w] = WL[(size_t)col * 512 + pair];
        }
        g_whfrag_hi[widx] = make_uint4(hi[0], hi[1], hi[2], hi[3]);
        g_whfrag_lo[widx] = make_uint4(lo[0], lo[1], lo[2], lo[3]);
        return;
    }

    // ---- phase-1 GEMM: 128x128 tile, 8 warps, warp 64x32, kt=32 ----
    __shared__ uint32_t sAh[128 * 20], sAl[128 * 20];
    __shared__ uint32_t sBh[128 * 20], sBl[128 * 20];

    const uint32_t* Xh = (const uint32_t*)g_xhi;
    const uint32_t* Xl = (const uint32_t*)g_xlo;
    const uint32_t* Wh = (const uint32_t*)g_WiT_hi;
    const uint32_t* Wl = (const uint32_t*)g_WiT_lo;

    const int bn   = (blk & 31) * 128;
    const int bm   = (blk >> 5) * 128;
    const int lane = tid & 31, wp = tid >> 5;
    const int g    = lane >> 2, tq = lane & 3;
    const int wm   = (wp >> 2) * 64;
    const int wn   = (wp & 3) * 32;
    const int r0   = wp * 2 + (lane >> 4);
    const int kw   = lane & 15;

    float acc[4][4][4] = {};
    uint32_t pAh[8], pAl[8], pBh[8], pBl[8];

    auto LOAD = [&](int kc) {
        int k0w = kc * 16;
#pragma unroll
        for (int i = 0; i < 8; i++) {
            int row = r0 + 16 * i;
            size_t ga = (size_t)(bm + row) * 512 + k0w + kw;
            size_t gb = (size_t)(bn + row) * 512 + k0w + kw;
            pAh[i] = Xh[ga]; pAl[i] = Xl[ga];
            pBh[i] = Wh[gb]; pBl[i] = Wl[gb];
        }
    };
    auto STORE = [&]() {
#pragma unroll
        for (int i = 0; i < 8; i++) {
            int row = r0 + 16 * i;
            sAh[row * 20 + kw] = pAh[i]; sAl[row * 20 + kw] = pAl[i];
            sBh[row * 20 + kw] = pBh[i]; sBl[row * 20 + kw] = pBl[i];
        }
    };

    LOAD(0); STORE(); __syncthreads();

    for (int kc = 0; kc < 32; kc++) {
        if (kc < 31) LOAD(kc + 1);
#pragma unroll
        for (int s = 0; s < 2; s++) {
            int kwb = s * 8;
            uint32_t bh[4][2], bl[4][2];
#pragma unroll
            for (int nf = 0; nf < 4; nf++) {
                int base = (wn + nf * 8 + g) * 20 + kwb + tq;
                bh[nf][0] = sBh[base]; bh[nf][1] = sBh[base + 4];
                bl[nf][0] = sBl[base]; bl[nf][1] = sBl[base + 4];
            }
#pragma unroll
            for (int mf = 0; mf < 4; mf++) {
                int rb = (wm + mf * 16 + g) * 20 + kwb + tq;
                uint32_t a0 = sAh[rb], a1 = sAh[rb + 160];
                uint32_t a2 = sAh[rb + 4], a3 = sAh[rb + 164];
                uint32_t l0 = sAl[rb], l1 = sAl[rb + 160];
                uint32_t l2 = sAl[rb + 4], l3 = sAl[rb + 164];
#pragma unroll
                for (int nf = 0; nf < 4; nf++) {
                    mma16816(acc[mf][nf], a0, a1, a2, a3, bh[nf][0], bh[nf][1]);
                    mma16816(acc[mf][nf], a0, a1, a2, a3, bl[nf][0], bl[nf][1]);
                    mma16816(acc[mf][nf], l0, l1, l2, l3, bh[nf][0], bh[nf][1]);
                }
            }
        }
        __syncthreads();
        if (kc < 31) { STORE(); __syncthreads(); }
    }

#pragma unroll
    for (int mf = 0; mf < 4; mf++) {
        int row0 = bm + wm + mf * 16 + g;
#pragma unroll
        for (int nf = 0; nf < 4; nf++) {
            int col = bn + wn + nf * 8 + tq * 2;
            float2 bb = *(const float2*)&bias[col];
            float2 v0, v1;
            v0.x = acc[mf][nf][0] + bb.x; v0.y = acc[mf][nf][1] + bb.y;
            v1.x = acc[mf][nf][2] + bb.x; v1.y = acc[mf][nf][3] + bb.y;
            *(float2*)&g_zx[(size_t)row0 * N4 + col]       = v0;
            *(float2*)&g_zx[(size_t)(row0 + 8) * N4 + col] = v1;
        }
    }
}

// ---------------------------------------------------------------------------
// Persistent recurrence (launch 3): 128 blocks x 256 thr.
// 8-slot register pipeline; zx/c_prev prefetched above the k-loop.
// ---------------------------------------------------------------------------
__global__ __launch_bounds__(256, 1)
void lstm_rec_mma(const float* __restrict__ c0,
                  float* __restrict__ ys,
                  float* __restrict__ cT,
                  float* __restrict__ hT)
{
    __shared__ float Z[64][33];

    const int tid  = threadIdx.x, bid = blockIdx.x;
    const int lane = tid & 31, wp = tid >> 5;
    const int gq   = lane >> 2, tq = lane & 3;
    const int m    = wp & 3;            // m16 block
    const int nhalf= wp >> 2;           // n16 half
    const int jb   = bid * 8;

    const uint4* WBh = g_whfrag_hi + ((size_t)(bid * 2 + nhalf) * 64) * 32;
    const uint4* WBl = g_whfrag_lo + ((size_t)(bid * 2 + nhalf) * 64) * 32;

    // pointwise decode
    const int pb  = tid >> 2;
    const int jj  = (tid & 3) * 2;
    const int j0  = jb + jj;
    const int p_g   = j0 >> 1;
    const int kcw   = p_g >> 3, within = p_g & 7;
    const int ptq   = within & 3, pwhi = within >> 2;
    const int pm    = pb >> 4, r16 = pb & 15;
    const int pg    = r16 & 7, ptop = r16 >> 3;
    const uint32_t hoff = (uint32_t)((((pm * 64 + kcw) * 32) + pg * 4 + ptq) * 4
                                     + pwhi * 2 + ptop);

    for (int t = 0; t < T_; t++) {
        const uint4* AH = g_hfrag_hi[t & 1] + m * 2048;
        const uint4* AL = g_hfrag_lo[t & 1] + m * 2048;

        // ---- prefetch pointwise operands (DRAM latency overlaps k-loop) ----
        const float* zx = g_zx + (size_t)t * BB * N4 + (size_t)pb * N4;
        const float* cp = (t == 0) ? c0 : cT;
        float2 xi = *(const float2*)&zx[j0];
        float2 xf = *(const float2*)&zx[HH + j0];
        float2 xg = *(const float2*)&zx[2 * HH + j0];
        float2 xo = *(const float2*)&zx[3 * HH + j0];
        float2 cv = *(const float2*)&cp[(size_t)pb * HH + j0];

        float acc0[4] = {}, acc1[4] = {};
        uint4 sAh[8], sAl[8], sBh[8], sBl[8];

#pragma unroll
        for (int s = 0; s < 8; s++) {
            sAh[s] = AH[s * 32 + lane];  sAl[s] = AL[s * 32 + lane];
            sBh[s] = WBh[s * 32 + lane]; sBl[s] = WBl[s * 32 + lane];
        }

#pragma unroll 8
        for (int kc = 0; kc < 64; kc++) {
            int cur = kc & 7;
            uint4 ah = sAh[cur], al = sAl[cur];
            uint4 bh = sBh[cur], bl = sBl[cur];
            if (kc + 8 < 64) {
                int nx = (kc + 8) * 32 + lane;
                sAh[cur] = AH[nx];  sAl[cur] = AL[nx];
                sBh[cur] = WBh[nx]; sBl[cur] = WBl[nx];
            }
            mma16816(acc0, ah.x, ah.y, ah.z, ah.w, bh.x, bh.y);
            mma16816(acc0, ah.x, ah.y, ah.z, ah.w, bl.x, bl.y);
            mma16816(acc0, al.x, al.y, al.z, al.w, bh.x, bh.y);
            mma16816(acc1, ah.x, ah.y, ah.z, ah.w, bh.z, bh.w);
            mma16816(acc1, ah.x, ah.y, ah.z, ah.w, bl.z, bl.w);
            mma16816(acc1, al.x, al.y, al.z, al.w, bh.z, bh.w);
        }

        // stage z tile
        {
            int mrow = m * 16, nb0 = nhalf * 16;
            int e0 = nb0 + tq * 2;
            Z[mrow + gq][e0]          = acc0[0];
            Z[mrow + gq][e0 + 1]      = acc0[1];
            Z[mrow + gq + 8][e0]      = acc0[2];
            Z[mrow + gq + 8][e0 + 1]  = acc0[3];
            int e1 = nb0 + 8 + tq * 2;
            Z[mrow + gq][e1]          = acc1[0];
            Z[mrow + gq][e1 + 1]      = acc1[1];
            Z[mrow + gq + 8][e1]      = acc1[2];
            Z[mrow + gq + 8][e1 + 1]  = acc1[3];
        }
        __syncthreads();

        // pointwise gates
        {
            float* ys_t = ys + (size_t)t * BB * HH;
            uint32_t* nhh = (uint32_t*)g_hfrag_hi[(t + 1) & 1];
            uint32_t* nhl = (uint32_t*)g_hfrag_lo[(t + 1) & 1];

            float h2[2], c2[2];
#pragma unroll
            for (int e = 0; e < 2; e++) {
                int zc = jj + e;
                float zi = Z[pb][zc]      + (e ? xi.y : xi.x);
                float zf = Z[pb][8 + zc]  + (e ? xf.y : xf.x);
                float zg = Z[pb][16 + zc] + (e ? xg.y : xg.x);
                float zo = Z[pb][24 + zc] + (e ? xo.y : xo.x);

                float ig = fast_sigmoid(zi);
                float fg = fast_sigmoid(zf);
                float gg = fast_tanh(zg);
                float og = fast_sigmoid(zo);

                float cc = fg * (e ? cv.y : cv.x) + ig * gg;
                c2[e] = cc;
                h2[e] = og * fast_tanh(cc);
            }

            *(float2*)&cT[(size_t)pb * HH + j0]   = *(float2*)c2;
            *(float2*)&ys_t[(size_t)pb * HH + j0] = *(float2*)h2;
            if (t == T_ - 1) *(float2*)&hT[(size_t)pb * HH + j0] = *(float2*)h2;

            __nv_bfloat16 h0b,l0b,h1b,l1b;
            bsplit(h2[0], h0b, l0b); bsplit(h2[1], h1b, l1b);
            __nv_bfloat162 wh; wh.x = h0b; wh.y = h1b;
            __nv_bfloat162 wl; wl.x = l0b; wl.y = l1b;
            nhh[hoff] = *(uint32_t*)&wh;
            nhl[hoff] = *(uint32_t*)&wl;
        }

        grid_barrier();
    }
}

// ---------------------------------------------------------------------------
extern "C" void kernel_launch(void* const* d_in, const int* in_sizes, int n_in,
                              void* d_out, int out_size)
{
    const float* x  = (const float*)d_in[0];   // [T,B,D]
    const float* c0 = (const float*)d_in[1];   // [B,H]
    const float* h0 = (const float*)d_in[2];   // [B,H]
    const float* Wi = (const float*)d_in[3];   // [D,4H]
    const float* Wh = (const float*)d_in[4];   // [H,4H]
    const float* b  = (const float*)d_in[5];   // [4H]

    float* out = (float*)d_out;
    float* ys = out;                                  // [T,B,H]
    float* cT = out + (size_t)T_ * BB * HH;           // [B,H]
    float* hT = cT + (size_t)BB * HH;                 // [B,H]

    prep_fused<<<16512, 256>>>(x, Wi, Wh, h0);        // launch 1
    gemm_wx_pack<<<10240, 256>>>(b);                  // launch 2
    lstm_rec_mma<<<RGRID, 256>>>(c0, ys, cT, hT);     // launch 3
}